// round 7
// baseline (speedup 1.0000x reference)
#include <cuda_runtime.h>
#include <cuda_bf16.h>
#include <cstdint>

#define Hh 768
#define Ss 128
#define Bb_ 8
#define Pp 8256            // S*(S+1)/2
#define NROWS 1024         // B*S
#define H4 192             // H/4
#define NX (NROWS * Hh)    // 786432
#define NW (Hh * Hh)       // 589824 per weight matrix

// fp32 activation outputs (pre-scaled by 0.5)
__device__ __align__(16) float g_A1[NX];
__device__ __align__(16) float g_A2[NX];
__device__ __align__(16) float g_Bb[NX];
__device__ __align__(16) float g_Gg[NX];
__device__ __align__(16) float g_Z[NX];     // (y - mean) * rstd (NOT scaled)

// pre-converted bf16 hi/lo operands
__device__ __align__(16) __nv_bfloat16 g_Xh[NX], g_Xl[NX];
__device__ __align__(16) __nv_bfloat16 g_Yh[NX], g_Yl[NX];
__device__ __align__(16) __nv_bfloat16 g_Wh[4 * NW], g_Wl[4 * NW];

// ---------------- PTX helpers ----------------

#define CP_ASYNC16(dst, src) \
    asm volatile("cp.async.cg.shared.global [%0], [%1], 16;" \
        :: "r"(dst), "l"(src) : "memory")
#define CP_COMMIT() asm volatile("cp.async.commit_group;" ::: "memory")
#define CP_WAIT(n)  asm volatile("cp.async.wait_group %0;" :: "n"(n) : "memory")

#define LDSM4(R, addr) \
    asm volatile("ldmatrix.sync.aligned.m8n8.x4.shared.b16 {%0,%1,%2,%3}, [%4];" \
        : "=r"((R)[0]), "=r"((R)[1]), "=r"((R)[2]), "=r"((R)[3]) : "r"(addr))

#define MMA16816(c, a, b0, b1) \
    asm volatile("mma.sync.aligned.m16n8k16.row.col.f32.bf16.bf16.f32 " \
        "{%0,%1,%2,%3},{%4,%5,%6,%7},{%8,%9},{%0,%1,%2,%3};" \
        : "+f"((c)[0]), "+f"((c)[1]), "+f"((c)[2]), "+f"((c)[3]) \
        : "r"((a)[0]), "r"((a)[1]), "r"((a)[2]), "r"((a)[3]), "r"(b0), "r"(b1))

// split float4 -> packed hi (uint2) / lo (uint2) bf16x4
__device__ __forceinline__ void split4(float4 v, uint2& hv, uint2& lv)
{
    __nv_bfloat162 h0 = __float22bfloat162_rn(make_float2(v.x, v.y));
    __nv_bfloat162 h1 = __float22bfloat162_rn(make_float2(v.z, v.w));
    float2 f0 = __bfloat1622float2(h0);
    float2 f1 = __bfloat1622float2(h1);
    __nv_bfloat162 l0 = __float22bfloat162_rn(make_float2(v.x - f0.x, v.y - f0.y));
    __nv_bfloat162 l1 = __float22bfloat162_rn(make_float2(v.z - f1.x, v.w - f1.y));
    hv.x = *(uint32_t*)&h0; hv.y = *(uint32_t*)&h1;
    lv.x = *(uint32_t*)&l0; lv.y = *(uint32_t*)&l1;
}

// ---------------- convert X + all W matrices to hi/lo bf16 -------------------
__global__ void __launch_bounds__(256) conv_kernel(
    const float* __restrict__ x, const float* __restrict__ catW,
    const float* __restrict__ betaW, const float* __restrict__ gammaW)
{
    const size_t gid = ((size_t)blockIdx.x * 256 + threadIdx.x) * 4;
    const float* src;
    __nv_bfloat16 *dh, *dl;
    if (gid < NX) {
        src = x + gid;
        dh = g_Xh + gid; dl = g_Xl + gid;
    } else {
        const size_t e = gid - NX;
        const int g = (int)(e / NW);
        const size_t rem = e - (size_t)g * NW;
        const int r = (int)(rem / Hh);
        const int k = (int)(rem % Hh);
        if (g == 0)      src = catW + (size_t)r * 2 * Hh + k;
        else if (g == 1) src = catW + (size_t)r * 2 * Hh + Hh + k;
        else if (g == 2) src = betaW + rem;
        else             src = gammaW + rem;
        dh = g_Wh + e; dl = g_Wl + e;
    }
    float4 v = *(const float4*)src;
    uint2 hv, lv;
    split4(v, hv, lv);
    *(uint2*)dh = hv;
    *(uint2*)dl = lv;
}

// ---------------- stats: mean/rstd + Z, and Y hi/lo conversion ---------------
__global__ void __launch_bounds__(256) stats_kernel(const float* __restrict__ Y)
{
    const int rowi = blockIdx.x * 8 + (threadIdx.x >> 5);
    const int lane = threadIdx.x & 31;
    const float4* p = (const float4*)(Y + (size_t)rowi * Hh);

    float4 v[6];
    float s = 0.f;
#pragma unroll
    for (int q = 0; q < 6; ++q) {
        v[q] = p[lane + 32 * q];
        s += v[q].x + v[q].y + v[q].z + v[q].w;
    }
#pragma unroll
    for (int o = 16; o; o >>= 1) s += __shfl_xor_sync(0xffffffffu, s, o);
    const float m = s * (1.0f / Hh);

    float ss = 0.f;
#pragma unroll
    for (int q = 0; q < 6; ++q) {
        float dx = v[q].x - m, dy = v[q].y - m, dz = v[q].z - m, dw = v[q].w - m;
        ss += dx * dx + dy * dy + dz * dz + dw * dw;
    }
#pragma unroll
    for (int o = 16; o; o >>= 1) ss += __shfl_xor_sync(0xffffffffu, ss, o);
    const float var = ss * (1.0f / Hh);
    float sd = var + 1e-12f;
    sd = sd * sd;                     // reference: std = (var+eps)**2
    const float rr = 1.0f / sd;

    float4* z = (float4*)(g_Z + (size_t)rowi * Hh);
#pragma unroll
    for (int q = 0; q < 6; ++q) {
        float4 o;
        o.x = (v[q].x - m) * rr; o.y = (v[q].y - m) * rr;
        o.z = (v[q].z - m) * rr; o.w = (v[q].w - m) * rr;
        z[lane + 32 * q] = o;
        uint2 hv, lv;
        split4(v[q], hv, lv);
        const size_t eo = (size_t)rowi * Hh + (lane + 32 * q) * 4;
        *(uint2*)(g_Yh + eo) = hv;
        *(uint2*)(g_Yl + eo) = lv;
    }
}

// ---------------- HMMA GEMM: 64x128 tiles, BK=32, cp.async double buffer -----
#define ST_AL  5120
#define ST_WH  10240
#define ST_WL  20480
#define STAGE  30720
#define SMEM_G (2 * STAGE)

struct GemmCtx {
    uint32_t sm0;
    uint32_t offA, a_off, b_off;
    const __nv_bfloat16 *Ah, *Al, *Wh0, *Wl0, *Wh1, *Wl1;
};

__device__ __forceinline__ void issue_stage(const GemmCtx& g, int s, int kc)
{
    const uint32_t b0 = g.sm0 + s * STAGE;
    const int ko = kc * 32;
    CP_ASYNC16(b0 + g.offA,                 g.Ah  + ko);
    CP_ASYNC16(b0 + ST_AL + g.offA,         g.Al  + ko);
    CP_ASYNC16(b0 + ST_WH + g.offA,         g.Wh0 + ko);
    CP_ASYNC16(b0 + ST_WH + g.offA + 5120,  g.Wh1 + ko);
    CP_ASYNC16(b0 + ST_WL + g.offA,         g.Wl0 + ko);
    CP_ASYNC16(b0 + ST_WL + g.offA + 5120,  g.Wl1 + ko);
    CP_COMMIT();
}

__device__ __forceinline__ void mma_stage(const GemmCtx& g, int s, float c[2][4][4])
{
    const uint32_t base = g.sm0 + s * STAGE;
#pragma unroll
    for (int kh = 0; kh < 2; ++kh) {
        const uint32_t ao = g.a_off + kh * 32;
        const uint32_t bo = g.b_off + kh * 32;
        uint32_t ah[2][4], al[2][4], bh[2][4], bl[2][4];
        LDSM4(ah[0], base + ao);
        LDSM4(ah[1], base + ao + 1280);
        LDSM4(al[0], base + ST_AL + ao);
        LDSM4(al[1], base + ST_AL + ao + 1280);
        LDSM4(bh[0], base + ST_WH + bo);
        LDSM4(bh[1], base + ST_WH + bo + 1280);
        LDSM4(bl[0], base + ST_WL + bo);
        LDSM4(bl[1], base + ST_WL + bo + 1280);
#pragma unroll
        for (int mt = 0; mt < 2; ++mt)
#pragma unroll
            for (int ntl = 0; ntl < 4; ++ntl) {
                const int p = ntl >> 1;
                const int q = (ntl & 1) * 2;
                MMA16816(c[mt][ntl], ah[mt], bh[p][q], bh[p][q + 1]);
                MMA16816(c[mt][ntl], ah[mt], bl[p][q], bl[p][q + 1]);
                MMA16816(c[mt][ntl], al[mt], bh[p][q], bh[p][q + 1]);
            }
    }
}

__global__ void __launch_bounds__(256, 3) gemm_hmma(
    const float* __restrict__ catb, const float* __restrict__ beta,
    const float* __restrict__ gamma)
{
    extern __shared__ __align__(16) char smem[];

    const int nt = blockIdx.x;          // 0..23
    const int bm = blockIdx.y * 64;
    const int grp = nt / 6;
    const int bn  = (nt % 6) * 128;

    const __nv_bfloat16* Abase_h = (grp == 1) ? g_Yh : g_Xh;
    const __nv_bfloat16* Abase_l = (grp == 1) ? g_Yl : g_Xl;
    const __nv_bfloat16* Wbase_h = g_Wh + (size_t)grp * NW;
    const __nv_bfloat16* Wbase_l = g_Wl + (size_t)grp * NW;

    const int tid  = threadIdx.x;
    const int lane = tid & 31;
    const int warp = tid >> 5;
    const int wm = (warp >> 2) * 32;
    const int wn = (warp & 3) * 32;

    GemmCtx g;
    g.sm0 = (uint32_t)__cvta_generic_to_shared(smem);
    const int r  = tid >> 2;
    const int cb = tid & 3;
    g.offA = (uint32_t)(r * 80 + cb * 16);
    g.Ah  = Abase_h + (size_t)(bm + r) * Hh + cb * 8;
    g.Al  = Abase_l + (size_t)(bm + r) * Hh + cb * 8;
    g.Wh0 = Wbase_h + (size_t)(bn + r) * Hh + cb * 8;
    g.Wl0 = Wbase_l + (size_t)(bn + r) * Hh + cb * 8;
    g.Wh1 = g.Wh0 + (size_t)64 * Hh;
    g.Wl1 = g.Wl0 + (size_t)64 * Hh;
    g.a_off = (uint32_t)(((wm + (lane & 15)) * 40 + (lane >> 4) * 8) * 2);
    g.b_off = (uint32_t)(((wn + (lane & 7) + ((lane >> 4) << 3)) * 40
                          + (((lane >> 3) & 1) * 8)) * 2);

    float c[2][4][4];
#pragma unroll
    for (int i = 0; i < 2; ++i)
#pragma unroll
        for (int j = 0; j < 4; ++j)
#pragma unroll
            for (int k = 0; k < 4; ++k) c[i][j][k] = 0.f;

    issue_stage(g, 0, 0);
    issue_stage(g, 1, 1);

#pragma unroll 2
    for (int kc = 0; kc < 24; ++kc) {
        if (kc == 23) { CP_WAIT(0); } else { CP_WAIT(1); }
        __syncthreads();
        const int s = kc & 1;
        mma_stage(g, s, c);
        __syncthreads();
        if (kc + 2 < 24) issue_stage(g, s, kc + 2);
    }

    float* OUT;
    const float* bias;
    if (grp == 0)      { OUT = g_A1; bias = catb;    }
    else if (grp == 1) { OUT = g_A2; bias = nullptr; }
    else if (grp == 2) { OUT = g_Bb; bias = beta;    }
    else               { OUT = g_Gg; bias = gamma;   }

    const int gq = lane >> 2;
    const int t2 = (lane & 3) * 2;
#pragma unroll
    for (int mt = 0; mt < 2; ++mt)
#pragma unroll
        for (int ntl = 0; ntl < 4; ++ntl) {
            const int col  = bn + wn + ntl * 8 + t2;
            float2 bv = make_float2(0.f, 0.f);
            if (bias) bv = *(const float2*)(bias + col);
            const int row0 = bm + wm + mt * 16 + gq;
            float2 o0, o1;
            // pre-scale by 0.5 (exact) so the output epilogue skips it
            o0.x = 0.5f * (c[mt][ntl][0] + bv.x); o0.y = 0.5f * (c[mt][ntl][1] + bv.y);
            o1.x = 0.5f * (c[mt][ntl][2] + bv.x); o1.y = 0.5f * (c[mt][ntl][3] + bv.y);
            *(float2*)(OUT + (size_t)row0 * Hh + col)       = o0;
            *(float2*)(OUT + (size_t)(row0 + 8) * Hh + col) = o1;
        }
}

// ---------------- fused output epilogue v3: smem-free, int addressing --------
// grid (80 valid (jc,ic4) pairs, 24 h-chunks, 8 b); block 256 = (32 j x 8 h4).
// Thread owns (j, h); 4 i's per block, a1/bb/gg via coalesced+broadcast LDG.
__global__ void __launch_bounds__(256) epilogue_kernel(float4* __restrict__ out)
{
    const int q = blockIdx.x;
    int jc, ic;
    if (q < 8)       { jc = 0; ic = q;      }
    else if (q < 24) { jc = 1; ic = q - 8;  }
    else if (q < 48) { jc = 2; ic = q - 24; }
    else             { jc = 3; ic = q - 48; }

    const int hc = blockIdx.y;
    const int b  = blockIdx.z;
    const int jl = threadIdx.x >> 3;
    const int hl = threadIdx.x & 7;

    const int j = jc * 32 + jl;
    const int h = hc * 8 + hl;          // float4 lane 0..191

    const float4* __restrict__ A1 = (const float4*)g_A1;
    const float4* __restrict__ A2 = (const float4*)g_A2;
    const float4* __restrict__ Bv = (const float4*)g_Bb;
    const float4* __restrict__ Gv = (const float4*)g_Gg;
    const float4* __restrict__ Z4 = (const float4*)g_Z;

    const int ry = (b * Ss + j) * H4 + h;
    const float4 a2 = A2[ry];
    const float4 zv = Z4[ry];

    const int i0 = ic * 4;
    const int bbase = b * Pp;

#pragma unroll
    for (int il = 0; il < 4; ++il) {
        const int i = i0 + il;
        if (i <= j) {
            const int rx = (b * Ss + i) * H4 + h;
            const float4 a1 = A1[rx];
            const float4 bb = Bv[rx];
            const float4 gg = Gv[rx];
            const int prow = bbase + i * Ss - (i * (i - 1)) / 2 + (j - i);
            float4 o;
            o.x = fmaxf(a1.x + a2.x, 0.f) + zv.x * gg.x + bb.x;
            o.y = fmaxf(a1.y + a2.y, 0.f) + zv.y * gg.y + bb.y;
            o.z = fmaxf(a1.z + a2.z, 0.f) + zv.z * gg.z + bb.z;
            o.w = fmaxf(a1.w + a2.w, 0.f) + zv.w * gg.w + bb.w;
            __stcs(&out[prow * H4 + h], o);
        }
    }
}

extern "C" void kernel_launch(void* const* d_in, const int* in_sizes, int n_in,
                              void* d_out, int out_size)
{
    const float* x      = (const float*)d_in[0];
    const float* y      = (const float*)d_in[1];
    const float* cat_W  = (const float*)d_in[2];
    const float* cat_b  = (const float*)d_in[3];
    const float* beta   = (const float*)d_in[4];
    const float* gamma  = (const float*)d_in[5];
    const float* beta_W = (const float*)d_in[6];
    const float* gammaW = (const float*)d_in[7];
    float* out = (float*)d_out;

    static int smem_set = 0;
    if (!smem_set) {
        cudaFuncSetAttribute(gemm_hmma, cudaFuncAttributeMaxDynamicSharedMemorySize, SMEM_G);
        smem_set = 1;
    }

    stats_kernel<<<NROWS / 8, 256>>>(y);

    const int conv_blocks = (NX + 4 * NW) / 4 / 256;   // 3072
    conv_kernel<<<conv_blocks, 256>>>(x, cat_W, beta_W, gammaW);

    dim3 ggrid(24, 16);
    gemm_hmma<<<ggrid, 256, SMEM_G>>>(cat_b, beta, gamma);

    dim3 egrid(80, 24, Bb_);
    epilogue_kernel<<<egrid, 256>>>((float4*)out);
}

// round 8
// speedup vs baseline: 1.0350x; 1.0350x over previous
#include <cuda_runtime.h>
#include <cuda_bf16.h>
#include <cstdint>

#define Hh 768
#define Ss 128
#define Bb_ 8
#define Pp 8256            // S*(S+1)/2
#define NROWS 1024         // B*S
#define H4 192             // H/4
#define NX (NROWS * Hh)    // 786432
#define NW (Hh * Hh)       // 589824 per weight matrix

// fp32 activation outputs (pre-scaled by 0.5)
__device__ __align__(16) float g_A1[NX];
__device__ __align__(16) float g_A2[NX];
__device__ __align__(16) float g_Bb[NX];
__device__ __align__(16) float g_Gg[NX];
__device__ __align__(16) float g_Z[NX];     // (y - mean) * rstd (NOT scaled)

// pre-converted bf16 hi/lo operands
__device__ __align__(16) __nv_bfloat16 g_Xh[NX], g_Xl[NX];
__device__ __align__(16) __nv_bfloat16 g_Yh[NX], g_Yl[NX];
__device__ __align__(16) __nv_bfloat16 g_Wh[4 * NW], g_Wl[4 * NW];

// ---------------- PTX helpers ----------------

#define CP_ASYNC16(dst, src) \
    asm volatile("cp.async.cg.shared.global [%0], [%1], 16;" \
        :: "r"(dst), "l"(src) : "memory")
#define CP_COMMIT() asm volatile("cp.async.commit_group;" ::: "memory")
#define CP_WAIT(n)  asm volatile("cp.async.wait_group %0;" :: "n"(n) : "memory")

#define LDSM4(R, addr) \
    asm volatile("ldmatrix.sync.aligned.m8n8.x4.shared.b16 {%0,%1,%2,%3}, [%4];" \
        : "=r"((R)[0]), "=r"((R)[1]), "=r"((R)[2]), "=r"((R)[3]) : "r"(addr))

#define MMA16816(c, a, b0, b1) \
    asm volatile("mma.sync.aligned.m16n8k16.row.col.f32.bf16.bf16.f32 " \
        "{%0,%1,%2,%3},{%4,%5,%6,%7},{%8,%9},{%0,%1,%2,%3};" \
        : "+f"((c)[0]), "+f"((c)[1]), "+f"((c)[2]), "+f"((c)[3]) \
        : "r"((a)[0]), "r"((a)[1]), "r"((a)[2]), "r"((a)[3]), "r"(b0), "r"(b1))

// split float4 -> packed hi (uint2) / lo (uint2) bf16x4
__device__ __forceinline__ void split4(float4 v, uint2& hv, uint2& lv)
{
    __nv_bfloat162 h0 = __float22bfloat162_rn(make_float2(v.x, v.y));
    __nv_bfloat162 h1 = __float22bfloat162_rn(make_float2(v.z, v.w));
    float2 f0 = __bfloat1622float2(h0);
    float2 f1 = __bfloat1622float2(h1);
    __nv_bfloat162 l0 = __float22bfloat162_rn(make_float2(v.x - f0.x, v.y - f0.y));
    __nv_bfloat162 l1 = __float22bfloat162_rn(make_float2(v.z - f1.x, v.w - f1.y));
    hv.x = *(uint32_t*)&h0; hv.y = *(uint32_t*)&h1;
    lv.x = *(uint32_t*)&l0; lv.y = *(uint32_t*)&l1;
}

// ---------------- convert X + all W matrices to hi/lo bf16 -------------------
__global__ void __launch_bounds__(256) conv_kernel(
    const float* __restrict__ x, const float* __restrict__ catW,
    const float* __restrict__ betaW, const float* __restrict__ gammaW)
{
    const size_t gid = ((size_t)blockIdx.x * 256 + threadIdx.x) * 4;
    const float* src;
    __nv_bfloat16 *dh, *dl;
    if (gid < NX) {
        src = x + gid;
        dh = g_Xh + gid; dl = g_Xl + gid;
    } else {
        const size_t e = gid - NX;
        const int g = (int)(e / NW);
        const size_t rem = e - (size_t)g * NW;
        const int r = (int)(rem / Hh);
        const int k = (int)(rem % Hh);
        if (g == 0)      src = catW + (size_t)r * 2 * Hh + k;
        else if (g == 1) src = catW + (size_t)r * 2 * Hh + Hh + k;
        else if (g == 2) src = betaW + rem;
        else             src = gammaW + rem;
        dh = g_Wh + e; dl = g_Wl + e;
    }
    float4 v = *(const float4*)src;
    uint2 hv, lv;
    split4(v, hv, lv);
    *(uint2*)dh = hv;
    *(uint2*)dl = lv;
}

// ---------------- stats: mean/rstd + Z, and Y hi/lo conversion ---------------
__global__ void __launch_bounds__(256) stats_kernel(const float* __restrict__ Y)
{
    const int rowi = blockIdx.x * 8 + (threadIdx.x >> 5);
    const int lane = threadIdx.x & 31;
    const float4* p = (const float4*)(Y + (size_t)rowi * Hh);

    float4 v[6];
    float s = 0.f;
#pragma unroll
    for (int q = 0; q < 6; ++q) {
        v[q] = p[lane + 32 * q];
        s += v[q].x + v[q].y + v[q].z + v[q].w;
    }
#pragma unroll
    for (int o = 16; o; o >>= 1) s += __shfl_xor_sync(0xffffffffu, s, o);
    const float m = s * (1.0f / Hh);

    float ss = 0.f;
#pragma unroll
    for (int q = 0; q < 6; ++q) {
        float dx = v[q].x - m, dy = v[q].y - m, dz = v[q].z - m, dw = v[q].w - m;
        ss += dx * dx + dy * dy + dz * dz + dw * dw;
    }
#pragma unroll
    for (int o = 16; o; o >>= 1) ss += __shfl_xor_sync(0xffffffffu, ss, o);
    const float var = ss * (1.0f / Hh);
    float sd = var + 1e-12f;
    sd = sd * sd;                     // reference: std = (var+eps)**2
    const float rr = 1.0f / sd;

    float4* z = (float4*)(g_Z + (size_t)rowi * Hh);
#pragma unroll
    for (int q = 0; q < 6; ++q) {
        float4 o;
        o.x = (v[q].x - m) * rr; o.y = (v[q].y - m) * rr;
        o.z = (v[q].z - m) * rr; o.w = (v[q].w - m) * rr;
        z[lane + 32 * q] = o;
        uint2 hv, lv;
        split4(v[q], hv, lv);
        const size_t eo = (size_t)rowi * Hh + (lane + 32 * q) * 4;
        *(uint2*)(g_Yh + eo) = hv;
        *(uint2*)(g_Yl + eo) = lv;
    }
}

// ---------------- HMMA GEMM: 64x128 tiles, BK=32, cp.async double buffer -----
#define ST_AL  5120
#define ST_WH  10240
#define ST_WL  20480
#define STAGE  30720
#define SMEM_G (2 * STAGE)

struct GemmCtx {
    uint32_t sm0;
    uint32_t offA, a_off, b_off;
    const __nv_bfloat16 *Ah, *Al, *Wh0, *Wl0, *Wh1, *Wl1;
};

__device__ __forceinline__ void issue_stage(const GemmCtx& g, int s, int kc)
{
    const uint32_t b0 = g.sm0 + s * STAGE;
    const int ko = kc * 32;
    CP_ASYNC16(b0 + g.offA,                 g.Ah  + ko);
    CP_ASYNC16(b0 + ST_AL + g.offA,         g.Al  + ko);
    CP_ASYNC16(b0 + ST_WH + g.offA,         g.Wh0 + ko);
    CP_ASYNC16(b0 + ST_WH + g.offA + 5120,  g.Wh1 + ko);
    CP_ASYNC16(b0 + ST_WL + g.offA,         g.Wl0 + ko);
    CP_ASYNC16(b0 + ST_WL + g.offA + 5120,  g.Wl1 + ko);
    CP_COMMIT();
}

__device__ __forceinline__ void mma_stage(const GemmCtx& g, int s, float c[2][4][4])
{
    const uint32_t base = g.sm0 + s * STAGE;
#pragma unroll
    for (int kh = 0; kh < 2; ++kh) {
        const uint32_t ao = g.a_off + kh * 32;
        const uint32_t bo = g.b_off + kh * 32;
        uint32_t ah[2][4], al[2][4], bh[2][4], bl[2][4];
        LDSM4(ah[0], base + ao);
        LDSM4(ah[1], base + ao + 1280);
        LDSM4(al[0], base + ST_AL + ao);
        LDSM4(al[1], base + ST_AL + ao + 1280);
        LDSM4(bh[0], base + ST_WH + bo);
        LDSM4(bh[1], base + ST_WH + bo + 1280);
        LDSM4(bl[0], base + ST_WL + bo);
        LDSM4(bl[1], base + ST_WL + bo + 1280);
#pragma unroll
        for (int mt = 0; mt < 2; ++mt)
#pragma unroll
            for (int ntl = 0; ntl < 4; ++ntl) {
                const int p = ntl >> 1;
                const int q = (ntl & 1) * 2;
                MMA16816(c[mt][ntl], ah[mt], bh[p][q], bh[p][q + 1]);
                MMA16816(c[mt][ntl], ah[mt], bl[p][q], bl[p][q + 1]);
                MMA16816(c[mt][ntl], al[mt], bh[p][q], bh[p][q + 1]);
            }
    }
}

__global__ void __launch_bounds__(256, 3) gemm_hmma(
    const float* __restrict__ catb, const float* __restrict__ beta,
    const float* __restrict__ gamma)
{
    extern __shared__ __align__(16) char smem[];

    const int nt = blockIdx.x;          // 0..23
    const int bm = blockIdx.y * 64;
    const int grp = nt / 6;
    const int bn  = (nt % 6) * 128;

    const __nv_bfloat16* Abase_h = (grp == 1) ? g_Yh : g_Xh;
    const __nv_bfloat16* Abase_l = (grp == 1) ? g_Yl : g_Xl;
    const __nv_bfloat16* Wbase_h = g_Wh + (size_t)grp * NW;
    const __nv_bfloat16* Wbase_l = g_Wl + (size_t)grp * NW;

    const int tid  = threadIdx.x;
    const int lane = tid & 31;
    const int warp = tid >> 5;
    const int wm = (warp >> 2) * 32;
    const int wn = (warp & 3) * 32;

    GemmCtx g;
    g.sm0 = (uint32_t)__cvta_generic_to_shared(smem);
    const int r  = tid >> 2;
    const int cb = tid & 3;
    g.offA = (uint32_t)(r * 80 + cb * 16);
    g.Ah  = Abase_h + (size_t)(bm + r) * Hh + cb * 8;
    g.Al  = Abase_l + (size_t)(bm + r) * Hh + cb * 8;
    g.Wh0 = Wbase_h + (size_t)(bn + r) * Hh + cb * 8;
    g.Wl0 = Wbase_l + (size_t)(bn + r) * Hh + cb * 8;
    g.Wh1 = g.Wh0 + (size_t)64 * Hh;
    g.Wl1 = g.Wl0 + (size_t)64 * Hh;
    g.a_off = (uint32_t)(((wm + (lane & 15)) * 40 + (lane >> 4) * 8) * 2);
    g.b_off = (uint32_t)(((wn + (lane & 7) + ((lane >> 4) << 3)) * 40
                          + (((lane >> 3) & 1) * 8)) * 2);

    float c[2][4][4];
#pragma unroll
    for (int i = 0; i < 2; ++i)
#pragma unroll
        for (int j = 0; j < 4; ++j)
#pragma unroll
            for (int k = 0; k < 4; ++k) c[i][j][k] = 0.f;

    issue_stage(g, 0, 0);
    issue_stage(g, 1, 1);

#pragma unroll 2
    for (int kc = 0; kc < 24; ++kc) {
        if (kc == 23) { CP_WAIT(0); } else { CP_WAIT(1); }
        __syncthreads();
        const int s = kc & 1;
        mma_stage(g, s, c);
        __syncthreads();
        if (kc + 2 < 24) issue_stage(g, s, kc + 2);
    }

    float* OUT;
    const float* bias;
    if (grp == 0)      { OUT = g_A1; bias = catb;    }
    else if (grp == 1) { OUT = g_A2; bias = nullptr; }
    else if (grp == 2) { OUT = g_Bb; bias = beta;    }
    else               { OUT = g_Gg; bias = gamma;   }

    const int gq = lane >> 2;
    const int t2 = (lane & 3) * 2;
#pragma unroll
    for (int mt = 0; mt < 2; ++mt)
#pragma unroll
        for (int ntl = 0; ntl < 4; ++ntl) {
            const int col  = bn + wn + ntl * 8 + t2;
            float2 bv = make_float2(0.f, 0.f);
            if (bias) bv = *(const float2*)(bias + col);
            const int row0 = bm + wm + mt * 16 + gq;
            float2 o0, o1;
            // pre-scale by 0.5 (exact) so the output epilogue skips it
            o0.x = 0.5f * (c[mt][ntl][0] + bv.x); o0.y = 0.5f * (c[mt][ntl][1] + bv.y);
            o1.x = 0.5f * (c[mt][ntl][2] + bv.x); o1.y = 0.5f * (c[mt][ntl][3] + bv.y);
            *(float2*)(OUT + (size_t)row0 * Hh + col)       = o0;
            *(float2*)(OUT + (size_t)(row0 + 8) * Hh + col) = o1;
        }
}

// ---------------- fused output epilogue v4 ------------------------------------
// Thread owns (i, h): a1/bb/gg live in REGISTERS; a2/z for 8 j's staged in smem.
// Inner loop: 2 LDS.128 + 1 predicated STG.128.
// grid (40 valid (ic,jc) pairs, 24 h-chunks, 8 b); block 256 = (32 i x 8 h4).
__global__ void __launch_bounds__(256) epilogue_kernel(float4* __restrict__ out)
{
    __shared__ float4 sA2[8][8], sZ[8][8];

    const int q = blockIdx.x;
    int ic, jc;
    if (q < 16)      { ic = 0; jc = q;           }
    else if (q < 28) { ic = 1; jc = q - 16 + 4;  }
    else if (q < 36) { ic = 2; jc = q - 28 + 8;  }
    else             { ic = 3; jc = q - 36 + 12; }

    const int hc = blockIdx.y;
    const int b  = blockIdx.z;
    const int tid = threadIdx.x;
    const int il = tid >> 3;            // 0..31
    const int hl = tid & 7;

    const int i = ic * 32 + il;
    const int h = hc * 8 + hl;          // float4 lane 0..191

    const float4* __restrict__ A1 = (const float4*)g_A1;
    const float4* __restrict__ A2 = (const float4*)g_A2;
    const float4* __restrict__ Bv = (const float4*)g_Bb;
    const float4* __restrict__ Gv = (const float4*)g_Gg;
    const float4* __restrict__ Z4 = (const float4*)g_Z;

    // stage a2/z for the 8 j's of this block
    if (tid < 64) {
        const int jl = tid >> 3;
        const int ry = (b * Ss + jc * 8 + jl) * H4 + h;
        sA2[jl][hl] = A2[ry];
        sZ[jl][hl]  = Z4[ry];
    }

    // per-thread row operands in registers
    const int rx = (b * Ss + i) * H4 + h;
    const float4 a1 = A1[rx];
    const float4 bb = Bv[rx];
    const float4 gg = Gv[rx];
    __syncthreads();

    // prow(i, j) = b*P + i*S - i(i-1)/2 + (j - i)
    const int rowbase = b * Pp + i * Ss - (i * (i - 1)) / 2 - i + jc * 8;

#pragma unroll
    for (int jl = 0; jl < 8; ++jl) {
        const int j = jc * 8 + jl;
        if (j >= i) {
            const float4 a2 = sA2[jl][hl];
            const float4 zv = sZ[jl][hl];
            float4 o;
            o.x = fmaxf(a1.x + a2.x, 0.f) + zv.x * gg.x + bb.x;
            o.y = fmaxf(a1.y + a2.y, 0.f) + zv.y * gg.y + bb.y;
            o.z = fmaxf(a1.z + a2.z, 0.f) + zv.z * gg.z + bb.z;
            o.w = fmaxf(a1.w + a2.w, 0.f) + zv.w * gg.w + bb.w;
            __stcs(&out[(rowbase + jl) * H4 + h], o);
        }
    }
}

extern "C" void kernel_launch(void* const* d_in, const int* in_sizes, int n_in,
                              void* d_out, int out_size)
{
    const float* x      = (const float*)d_in[0];
    const float* y      = (const float*)d_in[1];
    const float* cat_W  = (const float*)d_in[2];
    const float* cat_b  = (const float*)d_in[3];
    const float* beta   = (const float*)d_in[4];
    const float* gamma  = (const float*)d_in[5];
    const float* beta_W = (const float*)d_in[6];
    const float* gammaW = (const float*)d_in[7];
    float* out = (float*)d_out;

    static int smem_set = 0;
    if (!smem_set) {
        cudaFuncSetAttribute(gemm_hmma, cudaFuncAttributeMaxDynamicSharedMemorySize, SMEM_G);
        smem_set = 1;
    }

    stats_kernel<<<NROWS / 8, 256>>>(y);

    const int conv_blocks = (NX + 4 * NW) / 4 / 256;   // 3072
    conv_kernel<<<conv_blocks, 256>>>(x, cat_W, beta_W, gammaW);

    dim3 ggrid(24, 16);
    gemm_hmma<<<ggrid, 256, SMEM_G>>>(cat_b, beta, gamma);

    dim3 egrid(40, 24, Bb_);
    epilogue_kernel<<<egrid, 256>>>((float4*)out);
}

// round 9
// speedup vs baseline: 1.0453x; 1.0100x over previous
#include <cuda_runtime.h>
#include <cuda_bf16.h>
#include <cstdint>

#define Hh 768
#define Ss 128
#define Bb_ 8
#define Pp 8256            // S*(S+1)/2
#define NROWS 1024         // B*S
#define H4 192             // H/4
#define NX (NROWS * Hh)    // 786432
#define NW (Hh * Hh)       // 589824 per weight matrix

// fp32 activation outputs (pre-scaled by 0.5)
__device__ __align__(16) float g_A1[NX];
__device__ __align__(16) float g_A2[NX];
__device__ __align__(16) float g_Bb[NX];
__device__ __align__(16) float g_Gg[NX];
__device__ __align__(16) float g_Z[NX];     // (y - mean) * rstd (NOT scaled)

// combined hi/lo bf16 operands: lo lives at constant offset from hi
__device__ __align__(16) __nv_bfloat16 g_X2[2 * NX];       // hi [0,NX), lo [NX,2NX)
__device__ __align__(16) __nv_bfloat16 g_Y2[2 * NX];
__device__ __align__(16) __nv_bfloat16 g_W2[8 * NW];       // hi [g*NW], lo [(4+g)*NW]

// ---------------- PTX helpers ----------------

#define CP_ASYNC16(dst, src) \
    asm volatile("cp.async.cg.shared.global [%0], [%1], 16;" \
        :: "r"(dst), "l"(src) : "memory")
#define CP_COMMIT() asm volatile("cp.async.commit_group;" ::: "memory")
#define CP_WAIT(n)  asm volatile("cp.async.wait_group %0;" :: "n"(n) : "memory")

#define LDSM4(R, addr) \
    asm volatile("ldmatrix.sync.aligned.m8n8.x4.shared.b16 {%0,%1,%2,%3}, [%4];" \
        : "=r"((R)[0]), "=r"((R)[1]), "=r"((R)[2]), "=r"((R)[3]) : "r"(addr))

#define MMA16816(c, a, b0, b1) \
    asm volatile("mma.sync.aligned.m16n8k16.row.col.f32.bf16.bf16.f32 " \
        "{%0,%1,%2,%3},{%4,%5,%6,%7},{%8,%9},{%0,%1,%2,%3};" \
        : "+f"((c)[0]), "+f"((c)[1]), "+f"((c)[2]), "+f"((c)[3]) \
        : "r"((a)[0]), "r"((a)[1]), "r"((a)[2]), "r"((a)[3]), "r"(b0), "r"(b1))

// one 3-term-free MMA sweep: 2 m-tiles x 4 n-tiles with fragment sets A, B
#define MMA_SWEEP(c, A, B) do { \
    _Pragma("unroll") \
    for (int mt_ = 0; mt_ < 2; ++mt_) { \
        _Pragma("unroll") \
        for (int nl_ = 0; nl_ < 4; ++nl_) { \
            const int p_ = nl_ >> 1; \
            const int q_ = (nl_ & 1) * 2; \
            MMA16816((c)[mt_][nl_], (A)[mt_], (B)[p_][q_], (B)[p_][q_ + 1]); \
        } \
    } \
} while (0)

// split float4 -> packed hi (uint2) / lo (uint2) bf16x4
__device__ __forceinline__ void split4(float4 v, uint2& hv, uint2& lv)
{
    __nv_bfloat162 h0 = __float22bfloat162_rn(make_float2(v.x, v.y));
    __nv_bfloat162 h1 = __float22bfloat162_rn(make_float2(v.z, v.w));
    float2 f0 = __bfloat1622float2(h0);
    float2 f1 = __bfloat1622float2(h1);
    __nv_bfloat162 l0 = __float22bfloat162_rn(make_float2(v.x - f0.x, v.y - f0.y));
    __nv_bfloat162 l1 = __float22bfloat162_rn(make_float2(v.z - f1.x, v.w - f1.y));
    hv.x = *(uint32_t*)&h0; hv.y = *(uint32_t*)&h1;
    lv.x = *(uint32_t*)&l0; lv.y = *(uint32_t*)&l1;
}

// ---------------- merged prep: conv (blocks 0..3071) + stats (3072..3199) ----
__global__ void __launch_bounds__(256) prep_kernel(
    const float* __restrict__ x, const float* __restrict__ y,
    const float* __restrict__ catW,
    const float* __restrict__ betaW, const float* __restrict__ gammaW)
{
    if (blockIdx.x < 3072) {
        // conversion of X and the 4 weight matrices
        const size_t gid = ((size_t)blockIdx.x * 256 + threadIdx.x) * 4;
        const float* src;
        __nv_bfloat16 *dh, *dl;
        if (gid < NX) {
            src = x + gid;
            dh = g_X2 + gid; dl = g_X2 + NX + gid;
        } else {
            const size_t e = gid - NX;
            const int g = (int)(e / NW);
            const size_t rem = e - (size_t)g * NW;
            const int r = (int)(rem / Hh);
            const int k = (int)(rem % Hh);
            if (g == 0)      src = catW + (size_t)r * 2 * Hh + k;
            else if (g == 1) src = catW + (size_t)r * 2 * Hh + Hh + k;
            else if (g == 2) src = betaW + rem;
            else             src = gammaW + rem;
            dh = g_W2 + (size_t)g * NW + rem;
            dl = g_W2 + (size_t)(4 + g) * NW + rem;
        }
        float4 v = *(const float4*)src;
        uint2 hv, lv;
        split4(v, hv, lv);
        *(uint2*)dh = hv;
        *(uint2*)dl = lv;
        return;
    }

    // stats for 8 Y rows (warp per row)
    const int rowi = (blockIdx.x - 3072) * 8 + (threadIdx.x >> 5);
    const int lane = threadIdx.x & 31;
    const float4* p = (const float4*)(y + (size_t)rowi * Hh);

    float4 v[6];
    float s = 0.f;
#pragma unroll
    for (int q = 0; q < 6; ++q) {
        v[q] = p[lane + 32 * q];
        s += v[q].x + v[q].y + v[q].z + v[q].w;
    }
#pragma unroll
    for (int o = 16; o; o >>= 1) s += __shfl_xor_sync(0xffffffffu, s, o);
    const float m = s * (1.0f / Hh);

    float ss = 0.f;
#pragma unroll
    for (int q = 0; q < 6; ++q) {
        float dx = v[q].x - m, dy = v[q].y - m, dz = v[q].z - m, dw = v[q].w - m;
        ss += dx * dx + dy * dy + dz * dz + dw * dw;
    }
#pragma unroll
    for (int o = 16; o; o >>= 1) ss += __shfl_xor_sync(0xffffffffu, ss, o);
    const float var = ss * (1.0f / Hh);
    float sd = var + 1e-12f;
    sd = sd * sd;                     // reference: std = (var+eps)**2
    const float rr = 1.0f / sd;

    float4* z = (float4*)(g_Z + (size_t)rowi * Hh);
#pragma unroll
    for (int q = 0; q < 6; ++q) {
        float4 o;
        o.x = (v[q].x - m) * rr; o.y = (v[q].y - m) * rr;
        o.z = (v[q].z - m) * rr; o.w = (v[q].w - m) * rr;
        z[lane + 32 * q] = o;
        uint2 hv, lv;
        split4(v[q], hv, lv);
        const size_t eo = (size_t)rowi * Hh + (lane + 32 * q) * 4;
        *(uint2*)(g_Y2 + eo)      = hv;
        *(uint2*)(g_Y2 + NX + eo) = lv;
    }
}

// ---------------- HMMA GEMM: 64x128 tiles, BK=32, cp.async double buffer -----
#define ST_AL  5120
#define ST_WH  10240
#define ST_WL  20480
#define STAGE  30720
#define SMEM_G (2 * STAGE)

struct GemmCtx {
    uint32_t sm0;
    uint32_t offA, a_off, b_off;
    const __nv_bfloat16 *Ah, *Wh0, *Wh1;   // lo = base + constant element offset
};

__device__ __forceinline__ void issue_stage(const GemmCtx& g, int s, int kc)
{
    const uint32_t b0 = g.sm0 + s * STAGE;
    const int ko = kc * 32;
    CP_ASYNC16(b0 + g.offA,                 g.Ah  + ko);
    CP_ASYNC16(b0 + ST_AL + g.offA,         g.Ah  + NX + ko);        // Al
    CP_ASYNC16(b0 + ST_WH + g.offA,         g.Wh0 + ko);
    CP_ASYNC16(b0 + ST_WH + g.offA + 5120,  g.Wh1 + ko);
    CP_ASYNC16(b0 + ST_WL + g.offA,         g.Wh0 + 4 * NW + ko);    // Wl0
    CP_ASYNC16(b0 + ST_WL + g.offA + 5120,  g.Wh1 + 4 * NW + ko);    // Wl1
    CP_COMMIT();
}

// term-interleaved: max 3 fragment sets (24 regs) live at once
__device__ __forceinline__ void mma_stage(const GemmCtx& g, int s, float c[2][4][4])
{
    const uint32_t base = g.sm0 + s * STAGE;
#pragma unroll
    for (int kh = 0; kh < 2; ++kh) {
        const uint32_t ao = g.a_off + kh * 32;
        const uint32_t bo = g.b_off + kh * 32;
        uint32_t A[2][4], B[2][4], T[2][4];
        // term 1: Ah * Wh
        LDSM4(A[0], base + ao);
        LDSM4(A[1], base + ao + 1280);
        LDSM4(B[0], base + ST_WH + bo);
        LDSM4(B[1], base + ST_WH + bo + 1280);
        MMA_SWEEP(c, A, B);
        // term 2: Al * Wh (load Al into T, reuse B)
        LDSM4(T[0], base + ST_AL + ao);
        LDSM4(T[1], base + ST_AL + ao + 1280);
        MMA_SWEEP(c, T, B);
        // term 3: Ah * Wl (load Wl into T, reuse A)
        LDSM4(T[0], base + ST_WL + bo);
        LDSM4(T[1], base + ST_WL + bo + 1280);
        MMA_SWEEP(c, A, T);
    }
}

__global__ void __launch_bounds__(256, 3) gemm_hmma(
    const float* __restrict__ catb, const float* __restrict__ beta,
    const float* __restrict__ gamma)
{
    extern __shared__ __align__(16) char smem[];

    const int nt = blockIdx.x;          // 0..23
    const int bm = blockIdx.y * 64;
    const int grp = nt / 6;
    const int bn  = (nt % 6) * 128;

    const __nv_bfloat16* Abase = (grp == 1) ? g_Y2 : g_X2;
    const __nv_bfloat16* Wbase = g_W2 + (size_t)grp * NW;

    const int tid  = threadIdx.x;
    const int lane = tid & 31;
    const int warp = tid >> 5;
    const int wm = (warp >> 2) * 32;
    const int wn = (warp & 3) * 32;

    GemmCtx g;
    g.sm0 = (uint32_t)__cvta_generic_to_shared(smem);
    const int r  = tid >> 2;
    const int cb = tid & 3;
    g.offA = (uint32_t)(r * 80 + cb * 16);
    g.Ah  = Abase + (size_t)(bm + r) * Hh + cb * 8;
    g.Wh0 = Wbase + (size_t)(bn + r) * Hh + cb * 8;
    g.Wh1 = g.Wh0 + (size_t)64 * Hh;
    g.a_off = (uint32_t)(((wm + (lane & 15)) * 40 + (lane >> 4) * 8) * 2);
    g.b_off = (uint32_t)(((wn + (lane & 7) + ((lane >> 4) << 3)) * 40
                          + (((lane >> 3) & 1) * 8)) * 2);

    float c[2][4][4];
#pragma unroll
    for (int i = 0; i < 2; ++i)
#pragma unroll
        for (int j = 0; j < 4; ++j)
#pragma unroll
            for (int k = 0; k < 4; ++k) c[i][j][k] = 0.f;

    issue_stage(g, 0, 0);
    issue_stage(g, 1, 1);

#pragma unroll 2
    for (int kc = 0; kc < 24; ++kc) {
        if (kc == 23) { CP_WAIT(0); } else { CP_WAIT(1); }
        __syncthreads();
        const int s = kc & 1;
        mma_stage(g, s, c);
        __syncthreads();
        if (kc + 2 < 24) issue_stage(g, s, kc + 2);
    }

    float* OUT;
    const float* bias;
    if (grp == 0)      { OUT = g_A1; bias = catb;    }
    else if (grp == 1) { OUT = g_A2; bias = nullptr; }
    else if (grp == 2) { OUT = g_Bb; bias = beta;    }
    else               { OUT = g_Gg; bias = gamma;   }

    const int gq = lane >> 2;
    const int t2 = (lane & 3) * 2;
#pragma unroll
    for (int mt = 0; mt < 2; ++mt)
#pragma unroll
        for (int ntl = 0; ntl < 4; ++ntl) {
            const int col  = bn + wn + ntl * 8 + t2;
            float2 bv = make_float2(0.f, 0.f);
            if (bias) bv = *(const float2*)(bias + col);
            const int row0 = bm + wm + mt * 16 + gq;
            float2 o0, o1;
            // pre-scale by 0.5 (exact) so the output epilogue skips it
            o0.x = 0.5f * (c[mt][ntl][0] + bv.x); o0.y = 0.5f * (c[mt][ntl][1] + bv.y);
            o1.x = 0.5f * (c[mt][ntl][2] + bv.x); o1.y = 0.5f * (c[mt][ntl][3] + bv.y);
            *(float2*)(OUT + (size_t)row0 * Hh + col)       = o0;
            *(float2*)(OUT + (size_t)(row0 + 8) * Hh + col) = o1;
        }
}

// ---------------- fused output epilogue v4 (unchanged from R8) ---------------
__global__ void __launch_bounds__(256) epilogue_kernel(float4* __restrict__ out)
{
    __shared__ float4 sA2[8][8], sZ[8][8];

    const int q = blockIdx.x;
    int ic, jc;
    if (q < 16)      { ic = 0; jc = q;           }
    else if (q < 28) { ic = 1; jc = q - 16 + 4;  }
    else if (q < 36) { ic = 2; jc = q - 28 + 8;  }
    else             { ic = 3; jc = q - 36 + 12; }

    const int hc = blockIdx.y;
    const int b  = blockIdx.z;
    const int tid = threadIdx.x;
    const int il = tid >> 3;            // 0..31
    const int hl = tid & 7;

    const int i = ic * 32 + il;
    const int h = hc * 8 + hl;          // float4 lane 0..191

    const float4* __restrict__ A1 = (const float4*)g_A1;
    const float4* __restrict__ A2 = (const float4*)g_A2;
    const float4* __restrict__ Bv = (const float4*)g_Bb;
    const float4* __restrict__ Gv = (const float4*)g_Gg;
    const float4* __restrict__ Z4 = (const float4*)g_Z;

    if (tid < 64) {
        const int jl = tid >> 3;
        const int ry = (b * Ss + jc * 8 + jl) * H4 + h;
        sA2[jl][hl] = A2[ry];
        sZ[jl][hl]  = Z4[ry];
    }

    const int rx = (b * Ss + i) * H4 + h;
    const float4 a1 = A1[rx];
    const float4 bb = Bv[rx];
    const float4 gg = Gv[rx];
    __syncthreads();

    const int rowbase = b * Pp + i * Ss - (i * (i - 1)) / 2 - i + jc * 8;

#pragma unroll
    for (int jl = 0; jl < 8; ++jl) {
        const int j = jc * 8 + jl;
        if (j >= i) {
            const float4 a2 = sA2[jl][hl];
            const float4 zv = sZ[jl][hl];
            float4 o;
            o.x = fmaxf(a1.x + a2.x, 0.f) + zv.x * gg.x + bb.x;
            o.y = fmaxf(a1.y + a2.y, 0.f) + zv.y * gg.y + bb.y;
            o.z = fmaxf(a1.z + a2.z, 0.f) + zv.z * gg.z + bb.z;
            o.w = fmaxf(a1.w + a2.w, 0.f) + zv.w * gg.w + bb.w;
            __stcs(&out[(rowbase + jl) * H4 + h], o);
        }
    }
}

extern "C" void kernel_launch(void* const* d_in, const int* in_sizes, int n_in,
                              void* d_out, int out_size)
{
    const float* x      = (const float*)d_in[0];
    const float* y      = (const float*)d_in[1];
    const float* cat_W  = (const float*)d_in[2];
    const float* cat_b  = (const float*)d_in[3];
    const float* beta   = (const float*)d_in[4];
    const float* gamma  = (const float*)d_in[5];
    const float* beta_W = (const float*)d_in[6];
    const float* gammaW = (const float*)d_in[7];
    float* out = (float*)d_out;

    static int smem_set = 0;
    if (!smem_set) {
        cudaFuncSetAttribute(gemm_hmma, cudaFuncAttributeMaxDynamicSharedMemorySize, SMEM_G);
        smem_set = 1;
    }

    prep_kernel<<<3200, 256>>>(x, y, cat_W, beta_W, gammaW);

    dim3 ggrid(24, 16);
    gemm_hmma<<<ggrid, 256, SMEM_G>>>(cat_b, beta, gamma);

    dim3 egrid(40, 24, Bb_);
    epilogue_kernel<<<egrid, 256>>>((float4*)out);
}

// round 10
// speedup vs baseline: 1.5189x; 1.4530x over previous
#include <cuda_runtime.h>
#include <cuda_fp16.h>
#include <cstdint>

#define Hh 768
#define Ss 128
#define Bb_ 8
#define Pp 8256            // S*(S+1)/2
#define NROWS 1024         // B*S
#define H4 192             // H/4
#define NX (NROWS * Hh)    // 786432
#define NW (Hh * Hh)       // 589824 per weight matrix

// fp32 activation outputs (pre-scaled by 0.5)
__device__ __align__(16) float g_A1[NX];
__device__ __align__(16) float g_A2[NX];
__device__ __align__(16) float g_Bb[NX];
__device__ __align__(16) float g_Gg[NX];
__device__ __align__(16) float g_Z[NX];     // (y - mean) * rstd (NOT scaled)

// fp16 operands (single precision term — error ~4e-4 rms, under 1e-3 budget)
__device__ __align__(16) __half g_Xf[NX];
__device__ __align__(16) __half g_Yf[NX];
__device__ __align__(16) __half g_Wf[4 * NW];

// ---------------- PTX helpers ----------------

#define CP_ASYNC16(dst, src) \
    asm volatile("cp.async.cg.shared.global [%0], [%1], 16;" \
        :: "r"(dst), "l"(src) : "memory")
#define CP_COMMIT() asm volatile("cp.async.commit_group;" ::: "memory")
#define CP_WAIT(n)  asm volatile("cp.async.wait_group %0;" :: "n"(n) : "memory")

#define LDSM4(R, addr) \
    asm volatile("ldmatrix.sync.aligned.m8n8.x4.shared.b16 {%0,%1,%2,%3}, [%4];" \
        : "=r"((R)[0]), "=r"((R)[1]), "=r"((R)[2]), "=r"((R)[3]) : "r"(addr))

#define MMA16816F(c, a, b0, b1) \
    asm volatile("mma.sync.aligned.m16n8k16.row.col.f32.f16.f16.f32 " \
        "{%0,%1,%2,%3},{%4,%5,%6,%7},{%8,%9},{%0,%1,%2,%3};" \
        : "+f"((c)[0]), "+f"((c)[1]), "+f"((c)[2]), "+f"((c)[3]) \
        : "r"((a)[0]), "r"((a)[1]), "r"((a)[2]), "r"((a)[3]), "r"(b0), "r"(b1))

// float4 -> packed fp16x4
__device__ __forceinline__ uint2 cvt4(float4 v)
{
    __half2 h0 = __float22half2_rn(make_float2(v.x, v.y));
    __half2 h1 = __float22half2_rn(make_float2(v.z, v.w));
    uint2 r;
    r.x = *(uint32_t*)&h0; r.y = *(uint32_t*)&h1;
    return r;
}

// ---------------- merged prep: conv (blocks 0..3071) + stats (3072..3199) ----
__global__ void __launch_bounds__(256) prep_kernel(
    const float* __restrict__ x, const float* __restrict__ y,
    const float* __restrict__ catW,
    const float* __restrict__ betaW, const float* __restrict__ gammaW)
{
    if (blockIdx.x < 3072) {
        const size_t gid = ((size_t)blockIdx.x * 256 + threadIdx.x) * 4;
        const float* src;
        __half* dst;
        if (gid < NX) {
            src = x + gid;
            dst = g_Xf + gid;
        } else {
            const size_t e = gid - NX;
            const int g = (int)(e / NW);
            const size_t rem = e - (size_t)g * NW;
            const int r = (int)(rem / Hh);
            const int k = (int)(rem % Hh);
            if (g == 0)      src = catW + (size_t)r * 2 * Hh + k;
            else if (g == 1) src = catW + (size_t)r * 2 * Hh + Hh + k;
            else if (g == 2) src = betaW + rem;
            else             src = gammaW + rem;
            dst = g_Wf + e;
        }
        *(uint2*)dst = cvt4(*(const float4*)src);
        return;
    }

    // stats for 8 Y rows (warp per row)
    const int rowi = (blockIdx.x - 3072) * 8 + (threadIdx.x >> 5);
    const int lane = threadIdx.x & 31;
    const float4* p = (const float4*)(y + (size_t)rowi * Hh);

    float4 v[6];
    float s = 0.f;
#pragma unroll
    for (int q = 0; q < 6; ++q) {
        v[q] = p[lane + 32 * q];
        s += v[q].x + v[q].y + v[q].z + v[q].w;
    }
#pragma unroll
    for (int o = 16; o; o >>= 1) s += __shfl_xor_sync(0xffffffffu, s, o);
    const float m = s * (1.0f / Hh);

    float ss = 0.f;
#pragma unroll
    for (int q = 0; q < 6; ++q) {
        float dx = v[q].x - m, dy = v[q].y - m, dz = v[q].z - m, dw = v[q].w - m;
        ss += dx * dx + dy * dy + dz * dz + dw * dw;
    }
#pragma unroll
    for (int o = 16; o; o >>= 1) ss += __shfl_xor_sync(0xffffffffu, ss, o);
    const float var = ss * (1.0f / Hh);
    float sd = var + 1e-12f;
    sd = sd * sd;                     // reference: std = (var+eps)**2
    const float rr = 1.0f / sd;

    float4* z = (float4*)(g_Z + (size_t)rowi * Hh);
#pragma unroll
    for (int q = 0; q < 6; ++q) {
        float4 o;
        o.x = (v[q].x - m) * rr; o.y = (v[q].y - m) * rr;
        o.z = (v[q].z - m) * rr; o.w = (v[q].w - m) * rr;
        z[lane + 32 * q] = o;
        const size_t eo = (size_t)rowi * Hh + (lane + 32 * q) * 4;
        *(uint2*)(g_Yf + eo) = cvt4(v[q]);
    }
}

// ---------------- HMMA fp16 GEMM: 64x128 tiles, BK=32, cp.async dbl buffer ---
// stage: A[64 x 40h] = 5120 B | W[128 x 40h] = 10240 B
#define ST_W   5120
#define STAGE  15360
#define SMEM_G (2 * STAGE)

struct GemmCtx {
    uint32_t sm0;
    uint32_t offA, a_off, b_off;
    const __half *Ap, *Wp0, *Wp1;
};

__device__ __forceinline__ void issue_stage(const GemmCtx& g, int s, int kc)
{
    const uint32_t b0 = g.sm0 + s * STAGE;
    const int ko = kc * 32;
    CP_ASYNC16(b0 + g.offA,                g.Ap  + ko);
    CP_ASYNC16(b0 + ST_W + g.offA,         g.Wp0 + ko);
    CP_ASYNC16(b0 + ST_W + g.offA + 5120,  g.Wp1 + ko);
    CP_COMMIT();
}

__device__ __forceinline__ void mma_stage(const GemmCtx& g, int s, float c[2][4][4])
{
    const uint32_t base = g.sm0 + s * STAGE;
#pragma unroll
    for (int kh = 0; kh < 2; ++kh) {
        const uint32_t ao = g.a_off + kh * 32;
        const uint32_t bo = g.b_off + kh * 32;
        uint32_t A[2][4], B[2][4];
        LDSM4(A[0], base + ao);
        LDSM4(A[1], base + ao + 1280);
        LDSM4(B[0], base + ST_W + bo);
        LDSM4(B[1], base + ST_W + bo + 1280);
#pragma unroll
        for (int mt = 0; mt < 2; ++mt)
#pragma unroll
            for (int nl = 0; nl < 4; ++nl) {
                const int p = nl >> 1;
                const int q = (nl & 1) * 2;
                MMA16816F(c[mt][nl], A[mt], B[p][q], B[p][q + 1]);
            }
    }
}

__global__ void __launch_bounds__(256, 3) gemm_hmma(
    const float* __restrict__ catb, const float* __restrict__ beta,
    const float* __restrict__ gamma)
{
    extern __shared__ __align__(16) char smem[];

    const int nt = blockIdx.x;          // 0..23
    const int bm = blockIdx.y * 64;
    const int grp = nt / 6;
    const int bn  = (nt % 6) * 128;

    const __half* Abase = (grp == 1) ? g_Yf : g_Xf;
    const __half* Wbase = g_Wf + (size_t)grp * NW;

    const int tid  = threadIdx.x;
    const int lane = tid & 31;
    const int warp = tid >> 5;
    const int wm = (warp >> 2) * 32;
    const int wn = (warp & 3) * 32;

    GemmCtx g;
    g.sm0 = (uint32_t)__cvta_generic_to_shared(smem);
    const int r  = tid >> 2;
    const int cb = tid & 3;
    g.offA = (uint32_t)(r * 80 + cb * 16);
    g.Ap  = Abase + (size_t)(bm + r) * Hh + cb * 8;
    g.Wp0 = Wbase + (size_t)(bn + r) * Hh + cb * 8;
    g.Wp1 = g.Wp0 + (size_t)64 * Hh;
    g.a_off = (uint32_t)(((wm + (lane & 15)) * 40 + (lane >> 4) * 8) * 2);
    g.b_off = (uint32_t)(((wn + (lane & 7) + ((lane >> 4) << 3)) * 40
                          + (((lane >> 3) & 1) * 8)) * 2);

    float c[2][4][4];
#pragma unroll
    for (int i = 0; i < 2; ++i)
#pragma unroll
        for (int j = 0; j < 4; ++j)
#pragma unroll
            for (int k = 0; k < 4; ++k) c[i][j][k] = 0.f;

    issue_stage(g, 0, 0);
    issue_stage(g, 1, 1);

#pragma unroll 2
    for (int kc = 0; kc < 24; ++kc) {
        if (kc == 23) { CP_WAIT(0); } else { CP_WAIT(1); }
        __syncthreads();
        const int s = kc & 1;
        mma_stage(g, s, c);
        __syncthreads();
        if (kc + 2 < 24) issue_stage(g, s, kc + 2);
    }

    float* OUT;
    const float* bias;
    if (grp == 0)      { OUT = g_A1; bias = catb;    }
    else if (grp == 1) { OUT = g_A2; bias = nullptr; }
    else if (grp == 2) { OUT = g_Bb; bias = beta;    }
    else               { OUT = g_Gg; bias = gamma;   }

    const int gq = lane >> 2;
    const int t2 = (lane & 3) * 2;
#pragma unroll
    for (int mt = 0; mt < 2; ++mt)
#pragma unroll
        for (int ntl = 0; ntl < 4; ++ntl) {
            const int col  = bn + wn + ntl * 8 + t2;
            float2 bv = make_float2(0.f, 0.f);
            if (bias) bv = *(const float2*)(bias + col);
            const int row0 = bm + wm + mt * 16 + gq;
            float2 o0, o1;
            // pre-scale by 0.5 (exact) so the output epilogue skips it
            o0.x = 0.5f * (c[mt][ntl][0] + bv.x); o0.y = 0.5f * (c[mt][ntl][1] + bv.y);
            o1.x = 0.5f * (c[mt][ntl][2] + bv.x); o1.y = 0.5f * (c[mt][ntl][3] + bv.y);
            *(float2*)(OUT + (size_t)row0 * Hh + col)       = o0;
            *(float2*)(OUT + (size_t)(row0 + 8) * Hh + col) = o1;
        }
}

// ---------------- fused output epilogue v4 (plateau; unchanged) --------------
__global__ void __launch_bounds__(256) epilogue_kernel(float4* __restrict__ out)
{
    __shared__ float4 sA2[8][8], sZ[8][8];

    const int q = blockIdx.x;
    int ic, jc;
    if (q < 16)      { ic = 0; jc = q;           }
    else if (q < 28) { ic = 1; jc = q - 16 + 4;  }
    else if (q < 36) { ic = 2; jc = q - 28 + 8;  }
    else             { ic = 3; jc = q - 36 + 12; }

    const int hc = blockIdx.y;
    const int b  = blockIdx.z;
    const int tid = threadIdx.x;
    const int il = tid >> 3;            // 0..31
    const int hl = tid & 7;

    const int i = ic * 32 + il;
    const int h = hc * 8 + hl;          // float4 lane 0..191

    const float4* __restrict__ A1 = (const float4*)g_A1;
    const float4* __restrict__ A2 = (const float4*)g_A2;
    const float4* __restrict__ Bv = (const float4*)g_Bb;
    const float4* __restrict__ Gv = (const float4*)g_Gg;
    const float4* __restrict__ Z4 = (const float4*)g_Z;

    if (tid < 64) {
        const int jl = tid >> 3;
        const int ry = (b * Ss + jc * 8 + jl) * H4 + h;
        sA2[jl][hl] = A2[ry];
        sZ[jl][hl]  = Z4[ry];
    }

    const int rx = (b * Ss + i) * H4 + h;
    const float4 a1 = A1[rx];
    const float4 bb = Bv[rx];
    const float4 gg = Gv[rx];
    __syncthreads();

    const int rowbase = b * Pp + i * Ss - (i * (i - 1)) / 2 - i + jc * 8;

#pragma unroll
    for (int jl = 0; jl < 8; ++jl) {
        const int j = jc * 8 + jl;
        if (j >= i) {
            const float4 a2 = sA2[jl][hl];
            const float4 zv = sZ[jl][hl];
            float4 o;
            o.x = fmaxf(a1.x + a2.x, 0.f) + zv.x * gg.x + bb.x;
            o.y = fmaxf(a1.y + a2.y, 0.f) + zv.y * gg.y + bb.y;
            o.z = fmaxf(a1.z + a2.z, 0.f) + zv.z * gg.z + bb.z;
            o.w = fmaxf(a1.w + a2.w, 0.f) + zv.w * gg.w + bb.w;
            __stcs(&out[(rowbase + jl) * H4 + h], o);
        }
    }
}

extern "C" void kernel_launch(void* const* d_in, const int* in_sizes, int n_in,
                              void* d_out, int out_size)
{
    const float* x      = (const float*)d_in[0];
    const float* y      = (const float*)d_in[1];
    const float* cat_W  = (const float*)d_in[2];
    const float* cat_b  = (const float*)d_in[3];
    const float* beta   = (const float*)d_in[4];
    const float* gamma  = (const float*)d_in[5];
    const float* beta_W = (const float*)d_in[6];
    const float* gammaW = (const float*)d_in[7];
    float* out = (float*)d_out;

    static int smem_set = 0;
    if (!smem_set) {
        cudaFuncSetAttribute(gemm_hmma, cudaFuncAttributeMaxDynamicSharedMemorySize, SMEM_G);
        smem_set = 1;
    }

    prep_kernel<<<3200, 256>>>(x, y, cat_W, beta_W, gammaW);

    dim3 ggrid(24, 16);
    gemm_hmma<<<ggrid, 256, SMEM_G>>>(cat_b, beta, gamma);

    dim3 egrid(40, 24, Bb_);
    epilogue_kernel<<<egrid, 256>>>((float4*)out);
}

// round 11
// speedup vs baseline: 1.5307x; 1.0078x over previous
#include <cuda_runtime.h>
#include <cuda_fp16.h>
#include <cstdint>

#define Hh 768
#define Ss 128
#define Bb_ 8
#define Pp 8256            // S*(S+1)/2
#define NROWS 1024         // B*S
#define H4 192             // H/4
#define NX (NROWS * Hh)    // 786432
#define NW (Hh * Hh)       // 589824 per weight matrix
#define NX4 (NX / 4)       // 196608 float4s in X
#define NW4 (NW / 4)       // 147456 float4s per W

// fp32 activation outputs (pre-scaled by 0.5)
__device__ __align__(16) float g_A1[NX];
__device__ __align__(16) float g_A2[NX];
__device__ __align__(16) float g_Bb[NX];
__device__ __align__(16) float g_Gg[NX];
__device__ __align__(16) float g_Z[NX];     // (y - mean) * rstd (NOT scaled)

// fp16 operands (single precision term — measured rel_err 2.0e-4 < 1e-3)
__device__ __align__(16) __half g_Xf[NX];
__device__ __align__(16) __half g_Yf[NX];
__device__ __align__(16) __half g_Wf[4 * NW];

// ---------------- PTX helpers ----------------

#define CP_ASYNC16(dst, src) \
    asm volatile("cp.async.cg.shared.global [%0], [%1], 16;" \
        :: "r"(dst), "l"(src) : "memory")
#define CP_COMMIT() asm volatile("cp.async.commit_group;" ::: "memory")
#define CP_WAIT(n)  asm volatile("cp.async.wait_group %0;" :: "n"(n) : "memory")

#define LDSM4(R, addr) \
    asm volatile("ldmatrix.sync.aligned.m8n8.x4.shared.b16 {%0,%1,%2,%3}, [%4];" \
        : "=r"((R)[0]), "=r"((R)[1]), "=r"((R)[2]), "=r"((R)[3]) : "r"(addr))

#define MMA16816F(c, a, b0, b1) \
    asm volatile("mma.sync.aligned.m16n8k16.row.col.f32.f16.f16.f32 " \
        "{%0,%1,%2,%3},{%4,%5,%6,%7},{%8,%9},{%0,%1,%2,%3};" \
        : "+f"((c)[0]), "+f"((c)[1]), "+f"((c)[2]), "+f"((c)[3]) \
        : "r"((a)[0]), "r"((a)[1]), "r"((a)[2]), "r"((a)[3]), "r"(b0), "r"(b1))

// float4 -> packed fp16x4
__device__ __forceinline__ uint2 cvt4(float4 v)
{
    __half2 h0 = __float22half2_rn(make_float2(v.x, v.y));
    __half2 h1 = __float22half2_rn(make_float2(v.z, v.w));
    uint2 r;
    r.x = *(uint32_t*)&h0; r.y = *(uint32_t*)&h1;
    return r;
}

// ---------------- merged prep v2 ----------------------------------------------
// blocks [0,768):  convert X + 4 W matrices, 4 independent float4s per thread
// blocks [768,896): stats + Z + Y conversion (warp per row)
__global__ void __launch_bounds__(256) prep_kernel(
    const float* __restrict__ x, const float* __restrict__ y,
    const float* __restrict__ catW,
    const float* __restrict__ betaW, const float* __restrict__ gammaW)
{
    if (blockIdx.x < 768) {
        const int base4 = blockIdx.x * 1024 + threadIdx.x;   // float4 index
        const float4* src[4];
        __half* dst[4];
#pragma unroll
        for (int k = 0; k < 4; ++k) {
            const int g4 = base4 + k * 256;
            if (g4 < NX4) {
                src[k] = (const float4*)x + g4;
                dst[k] = g_Xf + (size_t)g4 * 4;
            } else {
                const int e4 = g4 - NX4;
                const int g = e4 / NW4;
                const int rem4 = e4 - g * NW4;
                const int r  = rem4 / (Hh / 4);
                const int k4 = rem4 - r * (Hh / 4);
                if (g == 0)      src[k] = (const float4*)(catW + (size_t)r * 2 * Hh) + k4;
                else if (g == 1) src[k] = (const float4*)(catW + (size_t)r * 2 * Hh + Hh) + k4;
                else if (g == 2) src[k] = (const float4*)betaW + rem4;
                else             src[k] = (const float4*)gammaW + rem4;
                dst[k] = g_Wf + (size_t)g * NW + (size_t)rem4 * 4;
            }
        }
        float4 v[4];
#pragma unroll
        for (int k = 0; k < 4; ++k) v[k] = *src[k];           // 4 loads in flight
#pragma unroll
        for (int k = 0; k < 4; ++k) *(uint2*)dst[k] = cvt4(v[k]);
        return;
    }

    // stats for 8 Y rows (warp per row)
    const int rowi = (blockIdx.x - 768) * 8 + (threadIdx.x >> 5);
    const int lane = threadIdx.x & 31;
    const float4* p = (const float4*)(y + (size_t)rowi * Hh);

    float4 v[6];
    float s = 0.f;
#pragma unroll
    for (int q = 0; q < 6; ++q) {
        v[q] = p[lane + 32 * q];
        s += v[q].x + v[q].y + v[q].z + v[q].w;
    }
#pragma unroll
    for (int o = 16; o; o >>= 1) s += __shfl_xor_sync(0xffffffffu, s, o);
    const float m = s * (1.0f / Hh);

    float ss = 0.f;
#pragma unroll
    for (int q = 0; q < 6; ++q) {
        float dx = v[q].x - m, dy = v[q].y - m, dz = v[q].z - m, dw = v[q].w - m;
        ss += dx * dx + dy * dy + dz * dz + dw * dw;
    }
#pragma unroll
    for (int o = 16; o; o >>= 1) ss += __shfl_xor_sync(0xffffffffu, ss, o);
    const float var = ss * (1.0f / Hh);
    float sd = var + 1e-12f;
    sd = sd * sd;                     // reference: std = (var+eps)**2
    const float rr = 1.0f / sd;

    float4* z = (float4*)(g_Z + (size_t)rowi * Hh);
#pragma unroll
    for (int q = 0; q < 6; ++q) {
        float4 o;
        o.x = (v[q].x - m) * rr; o.y = (v[q].y - m) * rr;
        o.z = (v[q].z - m) * rr; o.w = (v[q].w - m) * rr;
        z[lane + 32 * q] = o;
        const size_t eo = (size_t)rowi * Hh + (lane + 32 * q) * 4;
        *(uint2*)(g_Yf + eo) = cvt4(v[q]);
    }
}

// ---------------- HMMA fp16 GEMM: 64x128 tiles, BK=32, cp.async dbl buffer ---
// stage: A[64 x 40h] = 5120 B | W[128 x 40h] = 10240 B
#define ST_W   5120
#define STAGE  15360
#define SMEM_G (2 * STAGE)

struct GemmCtx {
    uint32_t sm0;
    uint32_t offA, a_off, b_off;
    const __half *Ap, *Wp0, *Wp1;
};

__device__ __forceinline__ void issue_stage(const GemmCtx& g, int s, int kc)
{
    const uint32_t b0 = g.sm0 + s * STAGE;
    const int ko = kc * 32;
    CP_ASYNC16(b0 + g.offA,                g.Ap  + ko);
    CP_ASYNC16(b0 + ST_W + g.offA,         g.Wp0 + ko);
    CP_ASYNC16(b0 + ST_W + g.offA + 5120,  g.Wp1 + ko);
    CP_COMMIT();
}

__device__ __forceinline__ void mma_stage(const GemmCtx& g, int s, float c[2][4][4])
{
    const uint32_t base = g.sm0 + s * STAGE;
#pragma unroll
    for (int kh = 0; kh < 2; ++kh) {
        const uint32_t ao = g.a_off + kh * 32;
        const uint32_t bo = g.b_off + kh * 32;
        uint32_t A[2][4], B[2][4];
        LDSM4(A[0], base + ao);
        LDSM4(A[1], base + ao + 1280);
        LDSM4(B[0], base + ST_W + bo);
        LDSM4(B[1], base + ST_W + bo + 1280);
#pragma unroll
        for (int mt = 0; mt < 2; ++mt)
#pragma unroll
            for (int nl = 0; nl < 4; ++nl) {
                const int p = nl >> 1;
                const int q = (nl & 1) * 2;
                MMA16816F(c[mt][nl], A[mt], B[p][q], B[p][q + 1]);
            }
    }
}

__global__ void __launch_bounds__(256, 3) gemm_hmma(
    const float* __restrict__ catb, const float* __restrict__ beta,
    const float* __restrict__ gamma)
{
    extern __shared__ __align__(16) char smem[];

    const int nt = blockIdx.x;          // 0..23
    const int bm = blockIdx.y * 64;
    const int grp = nt / 6;
    const int bn  = (nt % 6) * 128;

    const __half* Abase = (grp == 1) ? g_Yf : g_Xf;
    const __half* Wbase = g_Wf + (size_t)grp * NW;

    const int tid  = threadIdx.x;
    const int lane = tid & 31;
    const int warp = tid >> 5;
    const int wm = (warp >> 2) * 32;
    const int wn = (warp & 3) * 32;

    GemmCtx g;
    g.sm0 = (uint32_t)__cvta_generic_to_shared(smem);
    const int r  = tid >> 2;
    const int cb = tid & 3;
    g.offA = (uint32_t)(r * 80 + cb * 16);
    g.Ap  = Abase + (size_t)(bm + r) * Hh + cb * 8;
    g.Wp0 = Wbase + (size_t)(bn + r) * Hh + cb * 8;
    g.Wp1 = g.Wp0 + (size_t)64 * Hh;
    g.a_off = (uint32_t)(((wm + (lane & 15)) * 40 + (lane >> 4) * 8) * 2);
    g.b_off = (uint32_t)(((wn + (lane & 7) + ((lane >> 4) << 3)) * 40
                          + (((lane >> 3) & 1) * 8)) * 2);

    float c[2][4][4];
#pragma unroll
    for (int i = 0; i < 2; ++i)
#pragma unroll
        for (int j = 0; j < 4; ++j)
#pragma unroll
            for (int k = 0; k < 4; ++k) c[i][j][k] = 0.f;

    issue_stage(g, 0, 0);
    issue_stage(g, 1, 1);

#pragma unroll 2
    for (int kc = 0; kc < 24; ++kc) {
        if (kc == 23) { CP_WAIT(0); } else { CP_WAIT(1); }
        __syncthreads();
        const int s = kc & 1;
        mma_stage(g, s, c);
        __syncthreads();
        if (kc + 2 < 24) issue_stage(g, s, kc + 2);
    }

    float* OUT;
    const float* bias;
    if (grp == 0)      { OUT = g_A1; bias = catb;    }
    else if (grp == 1) { OUT = g_A2; bias = nullptr; }
    else if (grp == 2) { OUT = g_Bb; bias = beta;    }
    else               { OUT = g_Gg; bias = gamma;   }

    const int gq = lane >> 2;
    const int t2 = (lane & 3) * 2;
#pragma unroll
    for (int mt = 0; mt < 2; ++mt)
#pragma unroll
        for (int ntl = 0; ntl < 4; ++ntl) {
            const int col  = bn + wn + ntl * 8 + t2;
            float2 bv = make_float2(0.f, 0.f);
            if (bias) bv = *(const float2*)(bias + col);
            const int row0 = bm + wm + mt * 16 + gq;
            float2 o0, o1;
            // pre-scale by 0.5 (exact) so the output epilogue skips it
            o0.x = 0.5f * (c[mt][ntl][0] + bv.x); o0.y = 0.5f * (c[mt][ntl][1] + bv.y);
            o1.x = 0.5f * (c[mt][ntl][2] + bv.x); o1.y = 0.5f * (c[mt][ntl][3] + bv.y);
            *(float2*)(OUT + (size_t)row0 * Hh + col)       = o0;
            *(float2*)(OUT + (size_t)(row0 + 8) * Hh + col) = o1;
        }
}

// ---------------- fused output epilogue v4 (plateau; unchanged) --------------
__global__ void __launch_bounds__(256) epilogue_kernel(float4* __restrict__ out)
{
    __shared__ float4 sA2[8][8], sZ[8][8];

    const int q = blockIdx.x;
    int ic, jc;
    if (q < 16)      { ic = 0; jc = q;           }
    else if (q < 28) { ic = 1; jc = q - 16 + 4;  }
    else if (q < 36) { ic = 2; jc = q - 28 + 8;  }
    else             { ic = 3; jc = q - 36 + 12; }

    const int hc = blockIdx.y;
    const int b  = blockIdx.z;
    const int tid = threadIdx.x;
    const int il = tid >> 3;            // 0..31
    const int hl = tid & 7;

    const int i = ic * 32 + il;
    const int h = hc * 8 + hl;          // float4 lane 0..191

    const float4* __restrict__ A1 = (const float4*)g_A1;
    const float4* __restrict__ A2 = (const float4*)g_A2;
    const float4* __restrict__ Bv = (const float4*)g_Bb;
    const float4* __restrict__ Gv = (const float4*)g_Gg;
    const float4* __restrict__ Z4 = (const float4*)g_Z;

    if (tid < 64) {
        const int jl = tid >> 3;
        const int ry = (b * Ss + jc * 8 + jl) * H4 + h;
        sA2[jl][hl] = A2[ry];
        sZ[jl][hl]  = Z4[ry];
    }

    const int rx = (b * Ss + i) * H4 + h;
    const float4 a1 = A1[rx];
    const float4 bb = Bv[rx];
    const float4 gg = Gv[rx];
    __syncthreads();

    const int rowbase = b * Pp + i * Ss - (i * (i - 1)) / 2 - i + jc * 8;

#pragma unroll
    for (int jl = 0; jl < 8; ++jl) {
        const int j = jc * 8 + jl;
        if (j >= i) {
            const float4 a2 = sA2[jl][hl];
            const float4 zv = sZ[jl][hl];
            float4 o;
            o.x = fmaxf(a1.x + a2.x, 0.f) + zv.x * gg.x + bb.x;
            o.y = fmaxf(a1.y + a2.y, 0.f) + zv.y * gg.y + bb.y;
            o.z = fmaxf(a1.z + a2.z, 0.f) + zv.z * gg.z + bb.z;
            o.w = fmaxf(a1.w + a2.w, 0.f) + zv.w * gg.w + bb.w;
            __stcs(&out[(rowbase + jl) * H4 + h], o);
        }
    }
}

extern "C" void kernel_launch(void* const* d_in, const int* in_sizes, int n_in,
                              void* d_out, int out_size)
{
    const float* x      = (const float*)d_in[0];
    const float* y      = (const float*)d_in[1];
    const float* cat_W  = (const float*)d_in[2];
    const float* cat_b  = (const float*)d_in[3];
    const float* beta   = (const float*)d_in[4];
    const float* gamma  = (const float*)d_in[5];
    const float* beta_W = (const float*)d_in[6];
    const float* gammaW = (const float*)d_in[7];
    float* out = (float*)d_out;

    static int smem_set = 0;
    if (!smem_set) {
        cudaFuncSetAttribute(gemm_hmma, cudaFuncAttributeMaxDynamicSharedMemorySize, SMEM_G);
        smem_set = 1;
    }

    prep_kernel<<<896, 256>>>(x, y, cat_W, beta_W, gammaW);

    dim3 ggrid(24, 16);
    gemm_hmma<<<ggrid, 256, SMEM_G>>>(cat_b, beta, gamma);

    dim3 egrid(40, 24, Bb_);
    epilogue_kernel<<<egrid, 256>>>((float4*)out);
}

// round 12
// speedup vs baseline: 1.6318x; 1.0660x over previous
#include <cuda_runtime.h>
#include <cuda_fp16.h>
#include <cstdint>

#define Hh 768
#define Ss 128
#define Bb_ 8
#define Pp 8256            // S*(S+1)/2
#define NROWS 1024         // B*S
#define H4 192             // H/4
#define NX (NROWS * Hh)    // 786432
#define NW (Hh * Hh)       // 589824 per weight matrix
#define NX4 (NX / 4)       // 196608 float4s in X
#define NW4 (NW / 4)       // 147456 float4s per W

// fp32 activation outputs (pre-scaled by 0.5)
__device__ __align__(16) float g_A1[NX];
__device__ __align__(16) float g_A2[NX];
__device__ __align__(16) float g_Bb[NX];
__device__ __align__(16) float g_Gg[NX];
__device__ __align__(16) float g_Z[NX];     // (y - mean) * rstd (NOT scaled)

// fp16 operands (single precision term — measured rel_err 2.0e-4 < 1e-3)
__device__ __align__(16) __half g_Xf[NX];
__device__ __align__(16) __half g_Yf[NX];
__device__ __align__(16) __half g_Wf[4 * NW];

// ---------------- PTX helpers ----------------

#define CP_ASYNC16(dst, src) \
    asm volatile("cp.async.cg.shared.global [%0], [%1], 16;" \
        :: "r"(dst), "l"(src) : "memory")
#define CP_COMMIT() asm volatile("cp.async.commit_group;" ::: "memory")
#define CP_WAIT(n)  asm volatile("cp.async.wait_group %0;" :: "n"(n) : "memory")

#define LDSM4(R, addr) \
    asm volatile("ldmatrix.sync.aligned.m8n8.x4.shared.b16 {%0,%1,%2,%3}, [%4];" \
        : "=r"((R)[0]), "=r"((R)[1]), "=r"((R)[2]), "=r"((R)[3]) : "r"(addr))

#define MMA16816F(c, a, b0, b1) \
    asm volatile("mma.sync.aligned.m16n8k16.row.col.f32.f16.f16.f32 " \
        "{%0,%1,%2,%3},{%4,%5,%6,%7},{%8,%9},{%0,%1,%2,%3};" \
        : "+f"((c)[0]), "+f"((c)[1]), "+f"((c)[2]), "+f"((c)[3]) \
        : "r"((a)[0]), "r"((a)[1]), "r"((a)[2]), "r"((a)[3]), "r"(b0), "r"(b1))

// float4 -> packed fp16x4
__device__ __forceinline__ uint2 cvt4(float4 v)
{
    __half2 h0 = __float22half2_rn(make_float2(v.x, v.y));
    __half2 h1 = __float22half2_rn(make_float2(v.z, v.w));
    uint2 r;
    r.x = *(uint32_t*)&h0; r.y = *(uint32_t*)&h1;
    return r;
}

// ---------------- merged prep v3 ----------------------------------------------
// blocks [0,384):  convert X + 4 W matrices, 8 independent float4s per thread
// blocks [384,512): stats + Z + Y conversion (warp per row)
__global__ void __launch_bounds__(256) prep_kernel(
    const float* __restrict__ x, const float* __restrict__ y,
    const float* __restrict__ catW,
    const float* __restrict__ betaW, const float* __restrict__ gammaW)
{
    if (blockIdx.x < 384) {
        const int base4 = blockIdx.x * 2048 + threadIdx.x;   // float4 index
        const float4* src[8];
        __half* dst[8];
#pragma unroll
        for (int k = 0; k < 8; ++k) {
            const int g4 = base4 + k * 256;
            if (g4 < NX4) {
                src[k] = (const float4*)x + g4;
                dst[k] = g_Xf + (size_t)g4 * 4;
            } else {
                const int e4 = g4 - NX4;
                const int g = e4 / NW4;
                const int rem4 = e4 - g * NW4;
                const int r  = rem4 / (Hh / 4);
                const int k4 = rem4 - r * (Hh / 4);
                if (g == 0)      src[k] = (const float4*)(catW + (size_t)r * 2 * Hh) + k4;
                else if (g == 1) src[k] = (const float4*)(catW + (size_t)r * 2 * Hh + Hh) + k4;
                else if (g == 2) src[k] = (const float4*)betaW + rem4;
                else             src[k] = (const float4*)gammaW + rem4;
                dst[k] = g_Wf + (size_t)g * NW + (size_t)rem4 * 4;
            }
        }
        float4 v[8];
#pragma unroll
        for (int k = 0; k < 8; ++k) v[k] = *src[k];           // 8 loads in flight
#pragma unroll
        for (int k = 0; k < 8; ++k) *(uint2*)dst[k] = cvt4(v[k]);
        return;
    }

    // stats for 8 Y rows (warp per row)
    const int rowi = (blockIdx.x - 384) * 8 + (threadIdx.x >> 5);
    const int lane = threadIdx.x & 31;
    const float4* p = (const float4*)(y + (size_t)rowi * Hh);

    float4 v[6];
    float s = 0.f;
#pragma unroll
    for (int q = 0; q < 6; ++q) {
        v[q] = p[lane + 32 * q];
        s += v[q].x + v[q].y + v[q].z + v[q].w;
    }
#pragma unroll
    for (int o = 16; o; o >>= 1) s += __shfl_xor_sync(0xffffffffu, s, o);
    const float m = s * (1.0f / Hh);

    float ss = 0.f;
#pragma unroll
    for (int q = 0; q < 6; ++q) {
        float dx = v[q].x - m, dy = v[q].y - m, dz = v[q].z - m, dw = v[q].w - m;
        ss += dx * dx + dy * dy + dz * dz + dw * dw;
    }
#pragma unroll
    for (int o = 16; o; o >>= 1) ss += __shfl_xor_sync(0xffffffffu, ss, o);
    const float var = ss * (1.0f / Hh);
    float sd = var + 1e-12f;
    sd = sd * sd;                     // reference: std = (var+eps)**2
    const float rr = 1.0f / sd;

    float4* z = (float4*)(g_Z + (size_t)rowi * Hh);
#pragma unroll
    for (int q = 0; q < 6; ++q) {
        float4 o;
        o.x = (v[q].x - m) * rr; o.y = (v[q].y - m) * rr;
        o.z = (v[q].z - m) * rr; o.w = (v[q].w - m) * rr;
        z[lane + 32 * q] = o;
        const size_t eo = (size_t)rowi * Hh + (lane + 32 * q) * 4;
        *(uint2*)(g_Yf + eo) = cvt4(v[q]);
    }
}

// ---------------- HMMA fp16 GEMM: 64x128 tiles, BK=32, 3-stage cp.async ------
// stage: A[64 x 40h] = 5120 B | W[128 x 40h] = 10240 B
#define ST_W    5120
#define STAGE   15360
#define NSTAGE  3
#define SMEM_G  (NSTAGE * STAGE)

struct GemmCtx {
    uint32_t sm0;
    uint32_t offA, a_off, b_off;
    const __half *Ap, *Wp0, *Wp1;
};

__device__ __forceinline__ void issue_stage(const GemmCtx& g, int s, int kc)
{
    const uint32_t b0 = g.sm0 + s * STAGE;
    const int ko = kc * 32;
    CP_ASYNC16(b0 + g.offA,                g.Ap  + ko);
    CP_ASYNC16(b0 + ST_W + g.offA,         g.Wp0 + ko);
    CP_ASYNC16(b0 + ST_W + g.offA + 5120,  g.Wp1 + ko);
    CP_COMMIT();
}

__device__ __forceinline__ void mma_stage(const GemmCtx& g, int s, float c[2][4][4])
{
    const uint32_t base = g.sm0 + s * STAGE;
#pragma unroll
    for (int kh = 0; kh < 2; ++kh) {
        const uint32_t ao = g.a_off + kh * 32;
        const uint32_t bo = g.b_off + kh * 32;
        uint32_t A[2][4], B[2][4];
        LDSM4(A[0], base + ao);
        LDSM4(A[1], base + ao + 1280);
        LDSM4(B[0], base + ST_W + bo);
        LDSM4(B[1], base + ST_W + bo + 1280);
#pragma unroll
        for (int mt = 0; mt < 2; ++mt)
#pragma unroll
            for (int nl = 0; nl < 4; ++nl) {
                const int p = nl >> 1;
                const int q = (nl & 1) * 2;
                MMA16816F(c[mt][nl], A[mt], B[p][q], B[p][q + 1]);
            }
    }
}

__global__ void __launch_bounds__(256, 3) gemm_hmma(
    const float* __restrict__ catb, const float* __restrict__ beta,
    const float* __restrict__ gamma)
{
    extern __shared__ __align__(16) char smem[];

    const int nt = blockIdx.x;          // 0..23
    const int bm = blockIdx.y * 64;
    const int grp = nt / 6;
    const int bn  = (nt % 6) * 128;

    const __half* Abase = (grp == 1) ? g_Yf : g_Xf;
    const __half* Wbase = g_Wf + (size_t)grp * NW;

    const int tid  = threadIdx.x;
    const int lane = tid & 31;
    const int warp = tid >> 5;
    const int wm = (warp >> 2) * 32;
    const int wn = (warp & 3) * 32;

    GemmCtx g;
    g.sm0 = (uint32_t)__cvta_generic_to_shared(smem);
    const int r  = tid >> 2;
    const int cb = tid & 3;
    g.offA = (uint32_t)(r * 80 + cb * 16);
    g.Ap  = Abase + (size_t)(bm + r) * Hh + cb * 8;
    g.Wp0 = Wbase + (size_t)(bn + r) * Hh + cb * 8;
    g.Wp1 = g.Wp0 + (size_t)64 * Hh;
    g.a_off = (uint32_t)(((wm + (lane & 15)) * 40 + (lane >> 4) * 8) * 2);
    g.b_off = (uint32_t)(((wn + (lane & 7) + ((lane >> 4) << 3)) * 40
                          + (((lane >> 3) & 1) * 8)) * 2);

    float c[2][4][4];
#pragma unroll
    for (int i = 0; i < 2; ++i)
#pragma unroll
        for (int j = 0; j < 4; ++j)
#pragma unroll
            for (int k = 0; k < 4; ++k) c[i][j][k] = 0.f;

    issue_stage(g, 0, 0);
    issue_stage(g, 1, 1);

    // 3-stage ring, single sync per k-chunk.
    // top-of-iter sync guarantees all warps consumed slot (kc-1), so issuing
    // kc+2 into slot (kc+2)%3 == (kc-1)%3 right after it is safe.
#pragma unroll 3
    for (int kc = 0; kc < 24; ++kc) {
        const int s = kc % NSTAGE;
        CP_WAIT(1);                       // group kc landed
        __syncthreads();
        if (kc + 2 < 24) issue_stage(g, (kc + 2) % NSTAGE, kc + 2);
        mma_stage(g, s, c);
    }

    float* OUT;
    const float* bias;
    if (grp == 0)      { OUT = g_A1; bias = catb;    }
    else if (grp == 1) { OUT = g_A2; bias = nullptr; }
    else if (grp == 2) { OUT = g_Bb; bias = beta;    }
    else               { OUT = g_Gg; bias = gamma;   }

    const int gq = lane >> 2;
    const int t2 = (lane & 3) * 2;
#pragma unroll
    for (int mt = 0; mt < 2; ++mt)
#pragma unroll
        for (int ntl = 0; ntl < 4; ++ntl) {
            const int col  = bn + wn + ntl * 8 + t2;
            float2 bv = make_float2(0.f, 0.f);
            if (bias) bv = *(const float2*)(bias + col);
            const int row0 = bm + wm + mt * 16 + gq;
            float2 o0, o1;
            // pre-scale by 0.5 (exact) so the output epilogue skips it
            o0.x = 0.5f * (c[mt][ntl][0] + bv.x); o0.y = 0.5f * (c[mt][ntl][1] + bv.y);
            o1.x = 0.5f * (c[mt][ntl][2] + bv.x); o1.y = 0.5f * (c[mt][ntl][3] + bv.y);
            *(float2*)(OUT + (size_t)row0 * Hh + col)       = o0;
            *(float2*)(OUT + (size_t)(row0 + 8) * Hh + col) = o1;
        }
}

// ---------------- fused output epilogue v4 (write-ceiling plateau) -----------
__global__ void __launch_bounds__(256) epilogue_kernel(float4* __restrict__ out)
{
    __shared__ float4 sA2[8][8], sZ[8][8];

    const int q = blockIdx.x;
    int ic, jc;
    if (q < 16)      { ic = 0; jc = q;           }
    else if (q < 28) { ic = 1; jc = q - 16 + 4;  }
    else if (q < 36) { ic = 2; jc = q - 28 + 8;  }
    else             { ic = 3; jc = q - 36 + 12; }

    const int hc = blockIdx.y;
    const int b  = blockIdx.z;
    const int tid = threadIdx.x;
    const int il = tid >> 3;            // 0..31
    const int hl = tid & 7;

    const int i = ic * 32 + il;
    const int h = hc * 8 + hl;          // float4 lane 0..191

    const float4* __restrict__ A1 = (const float4*)g_A1;
    const float4* __restrict__ A2 = (const float4*)g_A2;
    const float4* __restrict__ Bv = (const float4*)g_Bb;
    const float4* __restrict__ Gv = (const float4*)g_Gg;
    const float4* __restrict__ Z4 = (const float4*)g_Z;

    if (tid < 64) {
        const int jl = tid >> 3;
        const int ry = (b * Ss + jc * 8 + jl) * H4 + h;
        sA2[jl][hl] = A2[ry];
        sZ[jl][hl]  = Z4[ry];
    }

    const int rx = (b * Ss + i) * H4 + h;
    const float4 a1 = A1[rx];
    const float4 bb = Bv[rx];
    const float4 gg = Gv[rx];
    __syncthreads();

    const int rowbase = b * Pp + i * Ss - (i * (i - 1)) / 2 - i + jc * 8;

#pragma unroll
    for (int jl = 0; jl < 8; ++jl) {
        const int j = jc * 8 + jl;
        if (j >= i) {
            const float4 a2 = sA2[jl][hl];
            const float4 zv = sZ[jl][hl];
            float4 o;
            o.x = fmaxf(a1.x + a2.x, 0.f) + zv.x * gg.x + bb.x;
            o.y = fmaxf(a1.y + a2.y, 0.f) + zv.y * gg.y + bb.y;
            o.z = fmaxf(a1.z + a2.z, 0.f) + zv.z * gg.z + bb.z;
            o.w = fmaxf(a1.w + a2.w, 0.f) + zv.w * gg.w + bb.w;
            __stcs(&out[(rowbase + jl) * H4 + h], o);
        }
    }
}

extern "C" void kernel_launch(void* const* d_in, const int* in_sizes, int n_in,
                              void* d_out, int out_size)
{
    const float* x      = (const float*)d_in[0];
    const float* y      = (const float*)d_in[1];
    const float* cat_W  = (const float*)d_in[2];
    const float* cat_b  = (const float*)d_in[3];
    const float* beta   = (const float*)d_in[4];
    const float* gamma  = (const float*)d_in[5];
    const float* beta_W = (const float*)d_in[6];
    const float* gammaW = (const float*)d_in[7];
    float* out = (float*)d_out;

    static int smem_set = 0;
    if (!smem_set) {
        cudaFuncSetAttribute(gemm_hmma, cudaFuncAttributeMaxDynamicSharedMemorySize, SMEM_G);
        smem_set = 1;
    }

    prep_kernel<<<512, 256>>>(x, y, cat_W, beta_W, gammaW);

    dim3 ggrid(24, 16);
    gemm_hmma<<<ggrid, 256, SMEM_G>>>(cat_b, beta, gamma);

    dim3 egrid(40, 24, Bb_);
    epilogue_kernel<<<egrid, 256>>>((float4*)out);
}